// round 13
// baseline (speedup 1.0000x reference)
#include <cuda_runtime.h>

#define HID 768
#define TPB 256
#define NW  (TPB / 32)     // 8 warps = 8 tokens per CTA
#define NCHUNK 6           // 6 chunks * 128 floats = 768
#define LN_EPS 1e-12f

struct SMem {
    float aw[HID], ab[HID], dw[HID], db[HID], g[HID], b[HID];
    float wbuf[NW][HID];   // cp.async landing zone for word-table rows
    float w0a, b0a, w0d, b0d;
};

__global__ void __launch_bounds__(TPB, 4) bert_emb_ln_kernel(
    const int*   __restrict__ word_ids,
    const int*   __restrict__ modal_ids,
    const int*   __restrict__ seg_ids,
    const int*   __restrict__ npi_ids,
    const int*   __restrict__ posi_ids,
    const float* __restrict__ age_tau,
    const float* __restrict__ delay_tau,
    const float* __restrict__ word_t,
    const float* __restrict__ modal_t,
    const float* __restrict__ seg_t,
    const float* __restrict__ npi_t,
    const float* __restrict__ posi_t,
    const float* __restrict__ age_w,   // [H-1]
    const float* __restrict__ age_b,   // [H-1]
    const float* __restrict__ age_w0,  // [1]
    const float* __restrict__ age_b0,  // [1]
    const float* __restrict__ del_w,
    const float* __restrict__ del_b,
    const float* __restrict__ del_w0,
    const float* __restrict__ del_b0,
    const float* __restrict__ gamma,
    const float* __restrict__ beta,
    float*       __restrict__ out)
{
    __shared__ SMem sm;

    const int tid  = threadIdx.x;
    const int lane = tid & 31;
    const int wid  = tid >> 5;

    // ---- one-time cooperative fill of per-CTA constants into smem.
    // Row 767 of the 4 time2vec arrays is zero-padded: sin(tau*0+0)=0, and
    // the linear term is added explicitly at (chunk 5, lane 31, .w).
    for (int i = tid; i < HID; i += TPB) {
        const bool v = i < HID - 1;
        sm.aw[i] = v ? __ldg(age_w + i) : 0.f;
        sm.ab[i] = v ? __ldg(age_b + i) : 0.f;
        sm.dw[i] = v ? __ldg(del_w + i) : 0.f;
        sm.db[i] = v ? __ldg(del_b + i) : 0.f;
        sm.g[i]  = __ldg(gamma + i);
        sm.b[i]  = __ldg(beta + i);
    }
    if (tid == 0) {
        sm.w0a = __ldg(age_w0); sm.b0a = __ldg(age_b0);
        sm.w0d = __ldg(del_w0); sm.b0d = __ldg(del_b0);
    }
    __syncthreads();   // the only block barrier

    // ---- warp-per-token
    const int tok = blockIdx.x * NW + wid;
    const int wi = __ldg(word_ids  + tok);
    const int mi = __ldg(modal_ids + tok);
    const int si = __ldg(seg_ids   + tok);
    const int ni = __ldg(npi_ids   + tok);
    const int pi = __ldg(posi_ids  + tok);
    const float at = __ldg(age_tau   + tok);
    const float dt = __ldg(delay_tau + tok);

    // ---- word row (DRAM-latency gather) via cp.async: no landing registers,
    // so its MLP is not bounded by the 64-reg budget.
    {
        const float4* wp = (const float4*)(word_t + (long long)wi * HID) + lane;
        unsigned int wdst =
            (unsigned int)__cvta_generic_to_shared(&sm.wbuf[wid][lane * 4]);
        #pragma unroll
        for (int j = 0; j < NCHUNK; j++) {
            asm volatile("cp.async.cg.shared.global [%0], [%1], 16;\n"
                         :: "r"(wdst + j * 512), "l"(wp + j * 32));
        }
        asm volatile("cp.async.commit_group;\n");
    }

    // ---- cheap-table gathers (L2/L1 resident) accumulate in registers
    const float4* mp = (const float4*)(modal_t + (long long)mi * HID) + lane;
    const float4* sp = (const float4*)(seg_t   + (long long)si * HID) + lane;
    const float4* np = (const float4*)(npi_t   + (long long)ni * HID) + lane;
    const float4* pp = (const float4*)(posi_t  + (long long)pi * HID) + lane;

    float4 x[NCHUNK];
    #pragma unroll
    for (int j = 0; j < NCHUNK; j++) {
        const float4 m = mp[j * 32];
        const float4 s = sp[j * 32];
        const float4 n = np[j * 32];
        const float4 p = pp[j * 32];
        x[j].x = m.x + s.x + n.x + p.x;
        x[j].y = m.y + s.y + n.y + p.y;
        x[j].z = m.z + s.z + n.z + p.z;
        x[j].w = m.w + s.w + n.w + p.w;
    }

    // ---- time2vec from smem constants (overlaps the in-flight cp.async)
    #pragma unroll
    for (int j = 0; j < NCHUNK; j++) {
        const int h = j * 128 + lane * 4;
        const float4 aw4 = *(const float4*)&sm.aw[h];
        const float4 ab4 = *(const float4*)&sm.ab[h];
        const float4 dw4 = *(const float4*)&sm.dw[h];
        const float4 db4 = *(const float4*)&sm.db[h];
        x[j].x += __sinf(fmaf(at, aw4.x, ab4.x)) + __sinf(fmaf(dt, dw4.x, db4.x));
        x[j].y += __sinf(fmaf(at, aw4.y, ab4.y)) + __sinf(fmaf(dt, dw4.y, db4.y));
        x[j].z += __sinf(fmaf(at, aw4.z, ab4.z)) + __sinf(fmaf(dt, dw4.z, db4.z));
        x[j].w += __sinf(fmaf(at, aw4.w, ab4.w)) + __sinf(fmaf(dt, dw4.w, db4.w));
        if (j == NCHUNK - 1 && lane == 31)  // h = 767: linear terms
            x[j].w += fmaf(at, sm.w0a, sm.b0a) + fmaf(dt, sm.w0d, sm.b0d);
    }

    // ---- fold in the word row from smem
    asm volatile("cp.async.wait_group 0;\n" ::: "memory");
    __syncwarp();
    #pragma unroll
    for (int j = 0; j < NCHUNK; j++) {
        const float4 wv = *(const float4*)&sm.wbuf[wid][j * 128 + lane * 4];
        x[j].x += wv.x; x[j].y += wv.y; x[j].z += wv.z; x[j].w += wv.w;
    }

    // ---- warp-only LN reduction (sum, sumsq), xor-butterfly, no barrier
    float s = 0.f, q = 0.f;
    #pragma unroll
    for (int j = 0; j < NCHUNK; j++) {
        s += x[j].x + x[j].y + x[j].z + x[j].w;
        q += x[j].x * x[j].x + x[j].y * x[j].y
           + x[j].z * x[j].z + x[j].w * x[j].w;
    }
    #pragma unroll
    for (int off = 16; off >= 1; off >>= 1) {
        s += __shfl_xor_sync(0xffffffffu, s, off);
        q += __shfl_xor_sync(0xffffffffu, q, off);
    }

    const float mu   = s * (1.0f / HID);
    const float var  = fmaf(q, 1.0f / HID, -mu * mu);
    const float rstd = rsqrtf(var + LN_EPS);

    // ---- normalize + affine + store (coalesced 512B per warp per chunk)
    float4* op = (float4*)(out + (long long)tok * HID) + lane;
    #pragma unroll
    for (int j = 0; j < NCHUNK; j++) {
        const int h = j * 128 + lane * 4;
        const float4 g4 = *(const float4*)&sm.g[h];
        const float4 b4 = *(const float4*)&sm.b[h];
        float4 o;
        o.x = fmaf((x[j].x - mu) * rstd, g4.x, b4.x);
        o.y = fmaf((x[j].y - mu) * rstd, g4.y, b4.y);
        o.z = fmaf((x[j].z - mu) * rstd, g4.z, b4.z);
        o.w = fmaf((x[j].w - mu) * rstd, g4.w, b4.w);
        op[j * 32] = o;
    }
}

extern "C" void kernel_launch(void* const* d_in, const int* in_sizes, int n_in,
                              void* d_out, int out_size) {
    const int*   word_ids  = (const int*)  d_in[0];
    const int*   modal_ids = (const int*)  d_in[1];
    const int*   seg_ids   = (const int*)  d_in[2];
    const int*   npi_ids   = (const int*)  d_in[3];
    const int*   posi_ids  = (const int*)  d_in[4];
    const float* age_tau   = (const float*)d_in[5];
    const float* delay_tau = (const float*)d_in[6];
    const float* word_t    = (const float*)d_in[7];
    const float* modal_t   = (const float*)d_in[8];
    const float* seg_t     = (const float*)d_in[9];
    const float* npi_t     = (const float*)d_in[10];
    const float* posi_t    = (const float*)d_in[11];
    const float* age_w     = (const float*)d_in[12];
    const float* age_b     = (const float*)d_in[13];
    const float* age_w0    = (const float*)d_in[14];
    const float* age_b0    = (const float*)d_in[15];
    const float* del_w     = (const float*)d_in[16];
    const float* del_b     = (const float*)d_in[17];
    const float* del_w0    = (const float*)d_in[18];
    const float* del_b0    = (const float*)d_in[19];
    const float* gamma     = (const float*)d_in[20];
    const float* beta      = (const float*)d_in[21];
    float* out = (float*)d_out;

    const int n_tokens = in_sizes[0];  // B*S = 16384, divisible by NW
    bert_emb_ln_kernel<<<n_tokens / NW, TPB>>>(
        word_ids, modal_ids, seg_ids, npi_ids, posi_ids,
        age_tau, delay_tau,
        word_t, modal_t, seg_t, npi_t, posi_t,
        age_w, age_b, age_w0, age_b0,
        del_w, del_b, del_w0, del_b0,
        gamma, beta, out);
}

// round 17
// speedup vs baseline: 1.4721x; 1.4721x over previous
#include <cuda_runtime.h>

#define HID 768
#define TPB 256
#define NW  (TPB / 32)     // 8 warps; 2 tokens per warp -> 16 tokens per CTA
#define TPW 2
#define NCHUNK 6           // 6 chunks * 128 floats = 768
#define LN_EPS 1e-12f

struct SMem {
    float aw[HID], ab[HID], dw[HID], db[HID], g[HID], b[HID];
    float w0a, b0a, w0d, b0d;
};

__global__ void __launch_bounds__(TPB, 3) bert_emb_ln_kernel(
    const int*   __restrict__ word_ids,
    const int*   __restrict__ modal_ids,
    const int*   __restrict__ seg_ids,
    const int*   __restrict__ npi_ids,
    const int*   __restrict__ posi_ids,
    const float* __restrict__ age_tau,
    const float* __restrict__ delay_tau,
    const float* __restrict__ word_t,
    const float* __restrict__ modal_t,
    const float* __restrict__ seg_t,
    const float* __restrict__ npi_t,
    const float* __restrict__ posi_t,
    const float* __restrict__ age_w,   // [H-1]
    const float* __restrict__ age_b,   // [H-1]
    const float* __restrict__ age_w0,  // [1]
    const float* __restrict__ age_b0,  // [1]
    const float* __restrict__ del_w,
    const float* __restrict__ del_b,
    const float* __restrict__ del_w0,
    const float* __restrict__ del_b0,
    const float* __restrict__ gamma,
    const float* __restrict__ beta,
    float*       __restrict__ out)
{
    __shared__ SMem sm;

    const int tid  = threadIdx.x;
    const int lane = tid & 31;
    const int wid  = tid >> 5;

    // ---- one-time cooperative fill of per-CTA constants into smem.
    // Row 767 of the 4 time2vec arrays is zero-padded: sin(tau*0+0)=0, and
    // the linear term is added explicitly at (chunk 5, lane 31, .w).
    for (int i = tid; i < HID; i += TPB) {
        const bool v = i < HID - 1;
        sm.aw[i] = v ? __ldg(age_w + i) : 0.f;
        sm.ab[i] = v ? __ldg(age_b + i) : 0.f;
        sm.dw[i] = v ? __ldg(del_w + i) : 0.f;
        sm.db[i] = v ? __ldg(del_b + i) : 0.f;
        sm.g[i]  = __ldg(gamma + i);
        sm.b[i]  = __ldg(beta + i);
    }
    if (tid == 0) {
        sm.w0a = __ldg(age_w0); sm.b0a = __ldg(age_b0);
        sm.w0d = __ldg(del_w0); sm.b0d = __ldg(del_b0);
    }
    __syncthreads();   // the only block barrier

    // ---- two tokens per warp: constants read from smem once, used twice
    const int tok0 = (blockIdx.x * NW + wid) * TPW;
    const int tok1 = tok0 + 1;

    const int wi0 = __ldg(word_ids  + tok0), wi1 = __ldg(word_ids  + tok1);
    const int mi0 = __ldg(modal_ids + tok0), mi1 = __ldg(modal_ids + tok1);
    const int si0 = __ldg(seg_ids   + tok0), si1 = __ldg(seg_ids   + tok1);
    const int ni0 = __ldg(npi_ids   + tok0), ni1 = __ldg(npi_ids   + tok1);
    const int pi0 = __ldg(posi_ids  + tok0), pi1 = __ldg(posi_ids  + tok1);
    const float at0 = __ldg(age_tau   + tok0), at1 = __ldg(age_tau   + tok1);
    const float dt0 = __ldg(delay_tau + tok0), dt1 = __ldg(delay_tau + tok1);

    const float4* wp0 = (const float4*)(word_t  + (long long)wi0 * HID) + lane;
    const float4* mp0 = (const float4*)(modal_t + (long long)mi0 * HID) + lane;
    const float4* sp0 = (const float4*)(seg_t   + (long long)si0 * HID) + lane;
    const float4* np0 = (const float4*)(npi_t   + (long long)ni0 * HID) + lane;
    const float4* pp0 = (const float4*)(posi_t  + (long long)pi0 * HID) + lane;
    const float4* wp1 = (const float4*)(word_t  + (long long)wi1 * HID) + lane;
    const float4* mp1 = (const float4*)(modal_t + (long long)mi1 * HID) + lane;
    const float4* sp1 = (const float4*)(seg_t   + (long long)si1 * HID) + lane;
    const float4* np1 = (const float4*)(npi_t   + (long long)ni1 * HID) + lane;
    const float4* pp1 = (const float4*)(posi_t  + (long long)pi1 * HID) + lane;

    // 60 independent LDG.128 across the two tokens — big MLP, no barriers
    float4 x0[NCHUNK], x1[NCHUNK];
    #pragma unroll
    for (int j = 0; j < NCHUNK; j++) {
        const float4 a0 = wp0[j * 32];
        const float4 m0 = mp0[j * 32];
        const float4 s0 = sp0[j * 32];
        const float4 n0 = np0[j * 32];
        const float4 p0 = pp0[j * 32];
        x0[j].x = a0.x + m0.x + s0.x + n0.x + p0.x;
        x0[j].y = a0.y + m0.y + s0.y + n0.y + p0.y;
        x0[j].z = a0.z + m0.z + s0.z + n0.z + p0.z;
        x0[j].w = a0.w + m0.w + s0.w + n0.w + p0.w;
        const float4 a1 = wp1[j * 32];
        const float4 m1 = mp1[j * 32];
        const float4 s1 = sp1[j * 32];
        const float4 n1 = np1[j * 32];
        const float4 p1 = pp1[j * 32];
        x1[j].x = a1.x + m1.x + s1.x + n1.x + p1.x;
        x1[j].y = a1.y + m1.y + s1.y + n1.y + p1.y;
        x1[j].z = a1.z + m1.z + s1.z + n1.z + p1.z;
        x1[j].w = a1.w + m1.w + s1.w + n1.w + p1.w;
    }

    // ---- time2vec: constants loaded once per chunk, applied to BOTH tokens
    #pragma unroll
    for (int j = 0; j < NCHUNK; j++) {
        const int h = j * 128 + lane * 4;
        const float4 aw4 = *(const float4*)&sm.aw[h];
        const float4 ab4 = *(const float4*)&sm.ab[h];
        const float4 dw4 = *(const float4*)&sm.dw[h];
        const float4 db4 = *(const float4*)&sm.db[h];
        x0[j].x += __sinf(fmaf(at0, aw4.x, ab4.x)) + __sinf(fmaf(dt0, dw4.x, db4.x));
        x0[j].y += __sinf(fmaf(at0, aw4.y, ab4.y)) + __sinf(fmaf(dt0, dw4.y, db4.y));
        x0[j].z += __sinf(fmaf(at0, aw4.z, ab4.z)) + __sinf(fmaf(dt0, dw4.z, db4.z));
        x0[j].w += __sinf(fmaf(at0, aw4.w, ab4.w)) + __sinf(fmaf(dt0, dw4.w, db4.w));
        x1[j].x += __sinf(fmaf(at1, aw4.x, ab4.x)) + __sinf(fmaf(dt1, dw4.x, db4.x));
        x1[j].y += __sinf(fmaf(at1, aw4.y, ab4.y)) + __sinf(fmaf(dt1, dw4.y, db4.y));
        x1[j].z += __sinf(fmaf(at1, aw4.z, ab4.z)) + __sinf(fmaf(dt1, dw4.z, db4.z));
        x1[j].w += __sinf(fmaf(at1, aw4.w, ab4.w)) + __sinf(fmaf(dt1, dw4.w, db4.w));
        if (j == NCHUNK - 1 && lane == 31) {  // h = 767: linear terms
            x0[j].w += fmaf(at0, sm.w0a, sm.b0a) + fmaf(dt0, sm.w0d, sm.b0d);
            x1[j].w += fmaf(at1, sm.w0a, sm.b0a) + fmaf(dt1, sm.w0d, sm.b0d);
        }
    }

    // ---- warp-only LN reductions for both tokens, xor-butterfly
    float s0 = 0.f, q0 = 0.f, s1 = 0.f, q1 = 0.f;
    #pragma unroll
    for (int j = 0; j < NCHUNK; j++) {
        s0 += x0[j].x + x0[j].y + x0[j].z + x0[j].w;
        q0 += x0[j].x * x0[j].x + x0[j].y * x0[j].y
            + x0[j].z * x0[j].z + x0[j].w * x0[j].w;
        s1 += x1[j].x + x1[j].y + x1[j].z + x1[j].w;
        q1 += x1[j].x * x1[j].x + x1[j].y * x1[j].y
            + x1[j].z * x1[j].z + x1[j].w * x1[j].w;
    }
    #pragma unroll
    for (int off = 16; off >= 1; off >>= 1) {
        s0 += __shfl_xor_sync(0xffffffffu, s0, off);
        q0 += __shfl_xor_sync(0xffffffffu, q0, off);
        s1 += __shfl_xor_sync(0xffffffffu, s1, off);
        q1 += __shfl_xor_sync(0xffffffffu, q1, off);
    }

    const float mu0   = s0 * (1.0f / HID);
    const float rstd0 = rsqrtf(fmaf(q0, 1.0f / HID, -mu0 * mu0) + LN_EPS);
    const float mu1   = s1 * (1.0f / HID);
    const float rstd1 = rsqrtf(fmaf(q1, 1.0f / HID, -mu1 * mu1) + LN_EPS);

    // ---- normalize + affine + store; g/b loaded once per chunk, used twice
    float4* op0 = (float4*)(out + (long long)tok0 * HID) + lane;
    float4* op1 = (float4*)(out + (long long)tok1 * HID) + lane;
    #pragma unroll
    for (int j = 0; j < NCHUNK; j++) {
        const int h = j * 128 + lane * 4;
        const float4 g4 = *(const float4*)&sm.g[h];
        const float4 b4 = *(const float4*)&sm.b[h];
        float4 o;
        o.x = fmaf((x0[j].x - mu0) * rstd0, g4.x, b4.x);
        o.y = fmaf((x0[j].y - mu0) * rstd0, g4.y, b4.y);
        o.z = fmaf((x0[j].z - mu0) * rstd0, g4.z, b4.z);
        o.w = fmaf((x0[j].w - mu0) * rstd0, g4.w, b4.w);
        op0[j * 32] = o;
        o.x = fmaf((x1[j].x - mu1) * rstd1, g4.x, b4.x);
        o.y = fmaf((x1[j].y - mu1) * rstd1, g4.y, b4.y);
        o.z = fmaf((x1[j].z - mu1) * rstd1, g4.z, b4.z);
        o.w = fmaf((x1[j].w - mu1) * rstd1, g4.w, b4.w);
        op1[j * 32] = o;
    }
}

extern "C" void kernel_launch(void* const* d_in, const int* in_sizes, int n_in,
                              void* d_out, int out_size) {
    const int*   word_ids  = (const int*)  d_in[0];
    const int*   modal_ids = (const int*)  d_in[1];
    const int*   seg_ids   = (const int*)  d_in[2];
    const int*   npi_ids   = (const int*)  d_in[3];
    const int*   posi_ids  = (const int*)  d_in[4];
    const float* age_tau   = (const float*)d_in[5];
    const float* delay_tau = (const float*)d_in[6];
    const float* word_t    = (const float*)d_in[7];
    const float* modal_t   = (const float*)d_in[8];
    const float* seg_t     = (const float*)d_in[9];
    const float* npi_t     = (const float*)d_in[10];
    const float* posi_t    = (const float*)d_in[11];
    const float* age_w     = (const float*)d_in[12];
    const float* age_b     = (const float*)d_in[13];
    const float* age_w0    = (const float*)d_in[14];
    const float* age_b0    = (const float*)d_in[15];
    const float* del_w     = (const float*)d_in[16];
    const float* del_b     = (const float*)d_in[17];
    const float* del_w0    = (const float*)d_in[18];
    const float* del_b0    = (const float*)d_in[19];
    const float* gamma     = (const float*)d_in[20];
    const float* beta      = (const float*)d_in[21];
    float* out = (float*)d_out;

    const int n_tokens = in_sizes[0];  // B*S = 16384, divisible by NW*TPW
    bert_emb_ln_kernel<<<n_tokens / (NW * TPW), TPB>>>(
        word_ids, modal_ids, seg_ids, npi_ids, posi_ids,
        age_tau, delay_tau,
        word_t, modal_t, seg_t, npi_t, posi_t,
        age_w, age_b, age_w0, age_b0,
        del_w, del_b, del_w0, del_b0,
        gamma, beta, out);
}